// round 1
// baseline (speedup 1.0000x reference)
#include <cuda_runtime.h>
#include <cuda_bf16.h>
#include <math.h>

// Problem dims (fixed per reference)
#define Bz 64
#define Tz 512
#define Dz 2048
#define Hz 512
#define BT (Bz * Tz)          // 32768
#define NBLK 8                // H / 64 h-blocks for partial scores

// Scratch (allocation-free rule: __device__ globals)
__device__ float g_uh[Bz * Hz];          // Uh + ba, [B,H]
__device__ float g_partial[NBLK * BT];   // partial scores per h-block
__device__ float g_att[BT];              // softmax weights

// ---------------------------------------------------------------------------
// Kernel 1: Uh[b,h] = sum_d text[b,d] * Ua[d,h] + ba[h]
// grid (H/128, B/8), block 128. Each block: 128 h-cols x 8 b-rows.
// ---------------------------------------------------------------------------
__global__ void uh_kernel(const float* __restrict__ text,
                          const float* __restrict__ Ua,
                          const float* __restrict__ ba,
                          float* __restrict__ uh) {
    const int h  = blockIdx.x * 128 + threadIdx.x;
    const int b0 = blockIdx.y * 8;
    float acc[8] = {0.f, 0.f, 0.f, 0.f, 0.f, 0.f, 0.f, 0.f};
    __shared__ float ts[8][32];

    for (int d0 = 0; d0 < Dz; d0 += 32) {
        for (int v = threadIdx.x; v < 8 * 32; v += 128) {
            int i = v >> 5, k = v & 31;
            ts[i][k] = text[(b0 + i) * Dz + d0 + k];
        }
        __syncthreads();
        #pragma unroll
        for (int k = 0; k < 32; k++) {
            float u = Ua[(size_t)(d0 + k) * Hz + h];
            #pragma unroll
            for (int i = 0; i < 8; i++) acc[i] = fmaf(ts[i][k], u, acc[i]);
        }
        __syncthreads();
    }
    float bav = ba[h];
    #pragma unroll
    for (int i = 0; i < 8; i++) uh[(b0 + i) * Hz + h] = acc[i] + bav;
}

// ---------------------------------------------------------------------------
// Kernel 2: fused score GEMM.
// For CTA (bx, by): rows [bx*128, bx*128+128) of flattened (b,t),
// h-cols [by*64, by*64+64). Computes Ws tile over full K=2048, then
// epilogue: partial[by][row] = sum_{h in tile} Va[h]*tanh(Ws + Uh[b,h]).
// Note: 128 | 512, so all 128 rows of a CTA share the same b.
// block = 256 threads as 16x16, register tile 8x4.
// ---------------------------------------------------------------------------
__global__ __launch_bounds__(256)
void score_kernel(const float* __restrict__ frames,
                  const float* __restrict__ Wa,
                  const float* __restrict__ uh,
                  const float* __restrict__ Va,
                  float* __restrict__ partial) {
    __shared__ float As[128][36];   // padded: row stride 144B (16B-aligned)
    __shared__ float Bs[32][64];

    const int id = threadIdx.x;
    const int tx = id & 15;
    const int ty = id >> 4;
    const int row0 = blockIdx.x * 128;
    const int h0   = blockIdx.y * 64;

    float acc[8][4];
    #pragma unroll
    for (int i = 0; i < 8; i++)
        #pragma unroll
        for (int j = 0; j < 4; j++) acc[i][j] = 0.f;

    for (int d0 = 0; d0 < Dz; d0 += 32) {
        // A tile: 128x32 floats = 1024 float4, 4 per thread
        #pragma unroll
        for (int v = 0; v < 4; v++) {
            int idx = id + v * 256;
            int r   = idx >> 3;
            int k4  = (idx & 7) << 2;
            float4 f = *(const float4*)&frames[(size_t)(row0 + r) * Dz + d0 + k4];
            *(float4*)&As[r][k4] = f;
        }
        // B tile: 32x64 floats = 512 float4, 2 per thread
        #pragma unroll
        for (int v = 0; v < 2; v++) {
            int idx = id + v * 256;
            int k   = idx >> 4;
            int c4  = (idx & 15) << 2;
            float4 f = *(const float4*)&Wa[(size_t)(d0 + k) * Hz + h0 + c4];
            *(float4*)&Bs[k][c4] = f;
        }
        __syncthreads();

        #pragma unroll
        for (int k = 0; k < 32; k++) {
            float a[8], bb[4];
            #pragma unroll
            for (int i = 0; i < 8; i++) a[i] = As[ty + 16 * i][k];
            #pragma unroll
            for (int j = 0; j < 4; j++) bb[j] = Bs[k][tx + 16 * j];
            #pragma unroll
            for (int i = 0; i < 8; i++)
                #pragma unroll
                for (int j = 0; j < 4; j++)
                    acc[i][j] = fmaf(a[i], bb[j], acc[i][j]);
        }
        __syncthreads();
    }

    // Epilogue: tanh + Va-weighted reduce over the 64 h-cols of this tile.
    const int b = row0 >> 9;   // constant per CTA (128 | 512)
    float va[4], uhv[4];
    #pragma unroll
    for (int j = 0; j < 4; j++) {
        int h = h0 + tx + 16 * j;
        va[j]  = Va[h];
        uhv[j] = uh[b * Hz + h];
    }
    #pragma unroll
    for (int i = 0; i < 8; i++) {
        float s = 0.f;
        #pragma unroll
        for (int j = 0; j < 4; j++)
            s += va[j] * tanhf(acc[i][j] + uhv[j]);
        // reduce across the 16 tx lanes (width=16 keeps halves separate)
        #pragma unroll
        for (int off = 8; off; off >>= 1)
            s += __shfl_down_sync(0xffffffffu, s, off, 16);
        if (tx == 0) {
            int row = row0 + ty + 16 * i;
            partial[(size_t)blockIdx.y * BT + row] = s;
        }
    }
}

// ---------------------------------------------------------------------------
// Kernel 3: sum partials + softmax over T. One block per b, 512 threads.
// ---------------------------------------------------------------------------
__global__ __launch_bounds__(512)
void softmax_kernel(const float* __restrict__ partial,
                    float* __restrict__ att) {
    const int b = blockIdx.x;
    const int t = threadIdx.x;
    float s = 0.f;
    #pragma unroll
    for (int p = 0; p < NBLK; p++)
        s += partial[(size_t)p * BT + b * Tz + t];

    __shared__ float red[Tz];
    red[t] = s;
    __syncthreads();
    for (int off = 256; off; off >>= 1) {
        if (t < off) red[t] = fmaxf(red[t], red[t + off]);
        __syncthreads();
    }
    float m = red[0];
    __syncthreads();
    float e = expf(s - m);
    red[t] = e;
    __syncthreads();
    for (int off = 256; off; off >>= 1) {
        if (t < off) red[t] += red[t + off];
        __syncthreads();
    }
    att[b * Tz + t] = e * (1.0f / red[0]);
}

// ---------------------------------------------------------------------------
// Kernel 4: out[b,d] = sum_t att[b,t] * frames[b,t,d]
// grid (D/256, B), block 256. Streaming, coalesced over d.
// ---------------------------------------------------------------------------
__global__ __launch_bounds__(256)
void wsum_kernel(const float* __restrict__ frames,
                 const float* __restrict__ att,
                 float* __restrict__ out) {
    const int b = blockIdx.y;
    const int d = blockIdx.x * 256 + threadIdx.x;

    __shared__ float as[Tz];
    for (int t = threadIdx.x; t < Tz; t += 256) as[t] = att[b * Tz + t];
    __syncthreads();

    const float* fb = frames + (size_t)b * Tz * Dz + d;
    float acc0 = 0.f, acc1 = 0.f, acc2 = 0.f, acc3 = 0.f;
    #pragma unroll 2
    for (int t = 0; t < Tz; t += 4) {
        acc0 = fmaf(as[t + 0], fb[(size_t)(t + 0) * Dz], acc0);
        acc1 = fmaf(as[t + 1], fb[(size_t)(t + 1) * Dz], acc1);
        acc2 = fmaf(as[t + 2], fb[(size_t)(t + 2) * Dz], acc2);
        acc3 = fmaf(as[t + 3], fb[(size_t)(t + 3) * Dz], acc3);
    }
    out[b * Dz + d] = (acc0 + acc1) + (acc2 + acc3);
}

// ---------------------------------------------------------------------------
extern "C" void kernel_launch(void* const* d_in, const int* in_sizes, int n_in,
                              void* d_out, int out_size) {
    const float* frames = (const float*)d_in[0];   // [B,T,D]
    const float* text   = (const float*)d_in[1];   // [B,D]
    const float* Wa     = (const float*)d_in[2];   // [D,H]
    const float* Ua     = (const float*)d_in[3];   // [D,H]
    const float* Va     = (const float*)d_in[4];   // [H]
    const float* ba     = (const float*)d_in[5];   // [H]
    float* out          = (float*)d_out;           // [B,D]

    float *uh, *partial, *att;
    cudaGetSymbolAddress((void**)&uh, g_uh);
    cudaGetSymbolAddress((void**)&partial, g_partial);
    cudaGetSymbolAddress((void**)&att, g_att);

    // 1) Uh = text @ Ua + ba
    uh_kernel<<<dim3(Hz / 128, Bz / 8), 128>>>(text, Ua, ba, uh);

    // 2) fused score GEMM: partial scores per 64-wide h-block
    score_kernel<<<dim3(BT / 128, NBLK), 256>>>(frames, Wa, uh, Va, partial);

    // 3) softmax over T
    softmax_kernel<<<Bz, Tz>>>(partial, att);

    // 4) weighted sum over frames
    wsum_kernel<<<dim3(Dz / 256, Bz), 256>>>(frames, att, out);
}

// round 3
// speedup vs baseline: 3.2704x; 3.2704x over previous
#include <cuda_runtime.h>
#include <cuda_bf16.h>
#include <math.h>
#include <cstdint>

// Problem dims (fixed per reference)
#define Bz 64
#define Tz 512
#define Dz 2048
#define Hz 512
#define BT (Bz * Tz)          // 32768
#define NBLK 4                // H/128 h-blocks for partial scores

// Scratch (__device__ globals; allocation-free rule)
__device__ float g_uh[Bz * Hz];
__device__ float g_partial[NBLK * BT];
__device__ float g_att[BT];
__device__ __nv_bfloat16 g_WaT[Hz * Dz];   // Wa transposed -> [H, D] bf16
__device__ float g_wpart[4 * Bz * Dz];

// ---------------------------------------------------------------------------
// helpers
// ---------------------------------------------------------------------------
__device__ __forceinline__ uint32_t smem_u32(const void* p) {
    uint32_t a;
    asm("{ .reg .u64 t; cvta.to.shared.u64 t, %1; cvt.u32.u64 %0, t; }"
        : "=r"(a) : "l"(p));
    return a;
}

#define SWZ(o) ((o) ^ (((o) >> 3) & 0x70))

__device__ __forceinline__ void ldsm4(uint32_t* a, uint32_t addr) {
    asm volatile("ldmatrix.sync.aligned.m8n8.x4.shared.b16 {%0,%1,%2,%3}, [%4];"
                 : "=r"(a[0]), "=r"(a[1]), "=r"(a[2]), "=r"(a[3]) : "r"(addr));
}
__device__ __forceinline__ void ldsm2(uint32_t* b, uint32_t addr) {
    asm volatile("ldmatrix.sync.aligned.m8n8.x2.shared.b16 {%0,%1}, [%2];"
                 : "=r"(b[0]), "=r"(b[1]) : "r"(addr));
}
__device__ __forceinline__ void mma16816(float* c, const uint32_t* a,
                                         const uint32_t* b) {
    asm volatile(
        "mma.sync.aligned.m16n8k16.row.col.f32.bf16.bf16.f32 "
        "{%0,%1,%2,%3}, {%4,%5,%6,%7}, {%8,%9}, {%0,%1,%2,%3};"
        : "+f"(c[0]), "+f"(c[1]), "+f"(c[2]), "+f"(c[3])
        : "r"(a[0]), "r"(a[1]), "r"(a[2]), "r"(a[3]), "r"(b[0]), "r"(b[1]));
}
__device__ __forceinline__ float tanh_fast(float x) {
    float y;
    asm("tanh.approx.f32 %0, %1;" : "=f"(y) : "f"(x));
    return y;
}

// ---------------------------------------------------------------------------
// Kernel 0: WaT[n][k] = bf16(Wa[k][n])
// ---------------------------------------------------------------------------
__global__ void transpose_kernel(const float* __restrict__ Wa,
                                 __nv_bfloat16* __restrict__ WaT) {
    __shared__ float tile[32][33];
    const int k0 = blockIdx.x * 32, n0 = blockIdx.y * 32;
    for (int i = threadIdx.y; i < 32; i += 8)
        tile[i][threadIdx.x] = Wa[(size_t)(k0 + i) * Hz + n0 + threadIdx.x];
    __syncthreads();
    for (int i = threadIdx.y; i < 32; i += 8)
        WaT[(size_t)(n0 + i) * Dz + k0 + threadIdx.x] =
            __float2bfloat16(tile[threadIdx.x][i]);
}

// ---------------------------------------------------------------------------
// Kernel 1: Uh[b,h] = sum_d text[b,d] * Ua[d,h] + ba[h]   (fp32)
// ---------------------------------------------------------------------------
__global__ void uh_kernel(const float* __restrict__ text,
                          const float* __restrict__ Ua,
                          const float* __restrict__ ba,
                          float* __restrict__ uh) {
    const int h  = blockIdx.x * 128 + threadIdx.x;
    const int b0 = blockIdx.y * 8;
    float acc[8] = {0.f, 0.f, 0.f, 0.f, 0.f, 0.f, 0.f, 0.f};
    __shared__ float ts[8][32];

    for (int d0 = 0; d0 < Dz; d0 += 32) {
        for (int v = threadIdx.x; v < 8 * 32; v += 128) {
            int i = v >> 5, k = v & 31;
            ts[i][k] = text[(b0 + i) * Dz + d0 + k];
        }
        __syncthreads();
        #pragma unroll
        for (int k = 0; k < 32; k++) {
            float u = Ua[(size_t)(d0 + k) * Hz + h];
            #pragma unroll
            for (int i = 0; i < 8; i++) acc[i] = fmaf(ts[i][k], u, acc[i]);
        }
        __syncthreads();
    }
    float bav = ba[h];
    #pragma unroll
    for (int i = 0; i < 8; i++) uh[(b0 + i) * Hz + h] = acc[i] + bav;
}

// ---------------------------------------------------------------------------
// Kernel 2: bf16 HMMA score GEMM + fused tanh·Va epilogue.
// CTA tile: M=128 (one b; 128|512), N=128 h. K=2048 in 32 chunks of 64,
// double buffered. 8 warps as 2(M) x 4(N); warp tile 64x32; frags 4x4 m16n8.
// Epilogue: partial[by][row] = sum_{h in CTA tile} Va[h]*tanh(Ws+Uh).
// ---------------------------------------------------------------------------
#define A0_OFF 0u
#define A1_OFF 16384u
#define B0_OFF 32768u
#define B1_OFF 49152u
#define SM_TOTAL 65536
#define NCHUNK 32

__global__ __launch_bounds__(256, 1)
void score_hmma_kernel(const float* __restrict__ frames,
                       const __nv_bfloat16* __restrict__ WaT,
                       const float* __restrict__ uh,
                       const float* __restrict__ Va,
                       float* __restrict__ partial) {
    extern __shared__ char smem[];
    const uint32_t sbase = smem_u32(smem);
    const int tid = threadIdx.x;
    const int wid = tid >> 5, lane = tid & 31;
    const int warp_m = wid & 1, warp_n = wid >> 1;    // 2 x 4
    const int wm = warp_m * 64, wn = warp_n * 32;
    const int row0 = blockIdx.x * 128;
    const int h0   = blockIdx.y * 128;

    float acc[4][4][4];
    #pragma unroll
    for (int i = 0; i < 4; i++)
        #pragma unroll
        for (int j = 0; j < 4; j++)
            #pragma unroll
            for (int e = 0; e < 4; e++) acc[i][j][e] = 0.f;

    float4 pa[8], pb[4];

    // global -> regs for chunk c
    auto loadG = [&](int c) {
        const float* fA = frames + (size_t)row0 * Dz + c * 64;
        #pragma unroll
        for (int v = 0; v < 8; v++) {
            int idx = tid + v * 256;          // 128 rows x 16 float4
            int r = idx >> 4, c4 = (idx & 15) << 2;
            pa[v] = *(const float4*)(fA + (size_t)r * Dz + c4);
        }
        const __nv_bfloat16* fB = WaT + (size_t)h0 * Dz + c * 64;
        #pragma unroll
        for (int v = 0; v < 4; v++) {
            int idx = tid + v * 256;          // 128 rows x 8 x16B
            int n = idx >> 3, k8 = (idx & 7) << 3;
            pb[v] = *(const float4*)(fB + (size_t)n * Dz + k8);
        }
    };
    // regs -> smem buffer
    auto storeS = [&](uint32_t aoff, uint32_t boff) {
        #pragma unroll
        for (int v = 0; v < 8; v++) {
            int idx = tid + v * 256;
            int r = idx >> 4, c4 = (idx & 15) << 2;
            __nv_bfloat162 p0 = __floats2bfloat162_rn(pa[v].x, pa[v].y);
            __nv_bfloat162 p1 = __floats2bfloat162_rn(pa[v].z, pa[v].w);
            uint2 pk;
            pk.x = *(uint32_t*)&p0;
            pk.y = *(uint32_t*)&p1;
            *(uint2*)(smem + aoff + SWZ((uint32_t)(r * 128 + c4 * 2))) = pk;
        }
        #pragma unroll
        for (int v = 0; v < 4; v++) {
            int idx = tid + v * 256;
            int n = idx >> 3, k8 = (idx & 7) << 3;
            *(float4*)(smem + boff + SWZ((uint32_t)(n * 128 + k8 * 2))) = pb[v];
        }
    };
    // compute on buffer (aoff, boff): 4 k16-steps
    auto compute = [&](uint32_t aoff, uint32_t boff) {
        #pragma unroll
        for (int ks = 0; ks < 4; ks++) {
            const int k16 = ks * 16;
            uint32_t bfr[4][2];
            #pragma unroll
            for (int j = 0; j < 4; j++) {
                uint32_t off = (uint32_t)((wn + j * 8 + (lane & 7)) * 128 +
                                          (k16 + ((lane >> 3) & 1) * 8) * 2);
                ldsm2(bfr[j], sbase + boff + SWZ(off));
            }
            #pragma unroll
            for (int i = 0; i < 4; i++) {
                uint32_t afr[4];
                uint32_t off = (uint32_t)((wm + i * 16 + (lane & 15)) * 128 +
                                          (k16 + (lane >> 4) * 8) * 2);
                ldsm4(afr, sbase + aoff + SWZ(off));
                #pragma unroll
                for (int j = 0; j < 4; j++)
                    mma16816(acc[i][j], afr, bfr[j]);
            }
        }
    };

    loadG(0);
    storeS(A0_OFF, B0_OFF);
    __syncthreads();

    for (int i = 0; i < NCHUNK; i++) {
        const int p = i & 1;
        if (i + 1 < NCHUNK) loadG(i + 1);
        compute(p ? A1_OFF : A0_OFF, p ? B1_OFF : B0_OFF);
        if (i + 1 < NCHUNK) {
            __syncthreads();      // everyone done reading the other buffer
            storeS(p ? A0_OFF : A1_OFF, p ? B0_OFF : B1_OFF);
            __syncthreads();      // next buffer ready
        }
    }

    // ---- epilogue: tanh + Va-weighted sum over this CTA's 128 h-cols ----
    const int b = row0 >> 9;
    float va_r[8], uh_r[8];
    #pragma unroll
    for (int j = 0; j < 4; j++) {
        int col = h0 + wn + j * 8 + (lane & 3) * 2;
        va_r[j * 2 + 0] = __ldg(Va + col);
        va_r[j * 2 + 1] = __ldg(Va + col + 1);
        uh_r[j * 2 + 0] = __ldg(uh + b * Hz + col);
        uh_r[j * 2 + 1] = __ldg(uh + b * Hz + col + 1);
    }
    __syncthreads();
    float* red = (float*)smem;    // [128][4] overlay

    #pragma unroll
    for (int i = 0; i < 4; i++) {
        float s0 = 0.f, s1 = 0.f;
        #pragma unroll
        for (int j = 0; j < 4; j++) {
            s0 = fmaf(va_r[j*2+0], tanh_fast(acc[i][j][0] + uh_r[j*2+0]), s0);
            s0 = fmaf(va_r[j*2+1], tanh_fast(acc[i][j][1] + uh_r[j*2+1]), s0);
            s1 = fmaf(va_r[j*2+0], tanh_fast(acc[i][j][2] + uh_r[j*2+0]), s1);
            s1 = fmaf(va_r[j*2+1], tanh_fast(acc[i][j][3] + uh_r[j*2+1]), s1);
        }
        s0 += __shfl_xor_sync(0xffffffffu, s0, 1);
        s0 += __shfl_xor_sync(0xffffffffu, s0, 2);
        s1 += __shfl_xor_sync(0xffffffffu, s1, 1);
        s1 += __shfl_xor_sync(0xffffffffu, s1, 2);
        if ((lane & 3) == 0) {
            int r = wm + i * 16 + (lane >> 2);
            red[r * 4 + warp_n] = s0;
            red[(r + 8) * 4 + warp_n] = s1;
        }
    }
    __syncthreads();
    if (tid < 128) {
        float s = red[tid * 4] + red[tid * 4 + 1] +
                  red[tid * 4 + 2] + red[tid * 4 + 3];
        partial[(size_t)blockIdx.y * BT + row0 + tid] = s;
    }
}

// ---------------------------------------------------------------------------
// Kernel 3: sum partials + softmax over T. One block per b, 512 threads.
// ---------------------------------------------------------------------------
__global__ __launch_bounds__(512)
void softmax_kernel(const float* __restrict__ partial,
                    float* __restrict__ att) {
    const int b = blockIdx.x;
    const int t = threadIdx.x;
    float s = 0.f;
    #pragma unroll
    for (int p = 0; p < NBLK; p++)
        s += partial[(size_t)p * BT + b * Tz + t];

    __shared__ float red[Tz];
    red[t] = s;
    __syncthreads();
    for (int off = 256; off; off >>= 1) {
        if (t < off) red[t] = fmaxf(red[t], red[t + off]);
        __syncthreads();
    }
    float m = red[0];
    __syncthreads();
    float e = expf(s - m);
    red[t] = e;
    __syncthreads();
    for (int off = 256; off; off >>= 1) {
        if (t < off) red[t] += red[t + off];
        __syncthreads();
    }
    att[b * Tz + t] = e * (1.0f / red[0]);
}

// ---------------------------------------------------------------------------
// Kernel 4: wsum (4-way T split) + combine
// ---------------------------------------------------------------------------
__global__ __launch_bounds__(256)
void wsum_kernel(const float* __restrict__ frames,
                 const float* __restrict__ att,
                 float* __restrict__ wpart) {
    const int b = blockIdx.y, sp = blockIdx.z;
    const int d = (blockIdx.x * 256 + threadIdx.x) * 4;
    const int t0 = sp * 128;

    __shared__ float as[128];
    if (threadIdx.x < 128) as[threadIdx.x] = att[b * Tz + t0 + threadIdx.x];
    __syncthreads();

    const float* fb = frames + ((size_t)b * Tz + t0) * Dz + d;
    float4 a0 = {0,0,0,0}, a1 = {0,0,0,0}, a2 = {0,0,0,0}, a3 = {0,0,0,0};
    #pragma unroll 2
    for (int t = 0; t < 128; t += 4) {
        float4 f0 = *(const float4*)(fb + (size_t)(t + 0) * Dz);
        float4 f1 = *(const float4*)(fb + (size_t)(t + 1) * Dz);
        float4 f2 = *(const float4*)(fb + (size_t)(t + 2) * Dz);
        float4 f3 = *(const float4*)(fb + (size_t)(t + 3) * Dz);
        float w0 = as[t], w1 = as[t + 1], w2 = as[t + 2], w3 = as[t + 3];
        a0.x = fmaf(w0, f0.x, a0.x); a0.y = fmaf(w0, f0.y, a0.y);
        a0.z = fmaf(w0, f0.z, a0.z); a0.w = fmaf(w0, f0.w, a0.w);
        a1.x = fmaf(w1, f1.x, a1.x); a1.y = fmaf(w1, f1.y, a1.y);
        a1.z = fmaf(w1, f1.z, a1.z); a1.w = fmaf(w1, f1.w, a1.w);
        a2.x = fmaf(w2, f2.x, a2.x); a2.y = fmaf(w2, f2.y, a2.y);
        a2.z = fmaf(w2, f2.z, a2.z); a2.w = fmaf(w2, f2.w, a2.w);
        a3.x = fmaf(w3, f3.x, a3.x); a3.y = fmaf(w3, f3.y, a3.y);
        a3.z = fmaf(w3, f3.z, a3.z); a3.w = fmaf(w3, f3.w, a3.w);
    }
    float4 r;
    r.x = (a0.x + a1.x) + (a2.x + a3.x);
    r.y = (a0.y + a1.y) + (a2.y + a3.y);
    r.z = (a0.z + a1.z) + (a2.z + a3.z);
    r.w = (a0.w + a1.w) + (a2.w + a3.w);
    *(float4*)(wpart + (size_t)sp * (Bz * Dz) + b * Dz + d) = r;
}

__global__ __launch_bounds__(256)
void wsum_combine(const float* __restrict__ wpart, float* __restrict__ out) {
    const int i = (blockIdx.x * 256 + threadIdx.x) * 4;
    float4 a = *(const float4*)(wpart + i);
    float4 b4 = *(const float4*)(wpart + 1 * (Bz * Dz) + i);
    float4 c = *(const float4*)(wpart + 2 * (Bz * Dz) + i);
    float4 d4 = *(const float4*)(wpart + 3 * (Bz * Dz) + i);
    float4 r;
    r.x = (a.x + b4.x) + (c.x + d4.x);
    r.y = (a.y + b4.y) + (c.y + d4.y);
    r.z = (a.z + b4.z) + (c.z + d4.z);
    r.w = (a.w + b4.w) + (c.w + d4.w);
    *(float4*)(out + i) = r;
}

// ---------------------------------------------------------------------------
extern "C" void kernel_launch(void* const* d_in, const int* in_sizes, int n_in,
                              void* d_out, int out_size) {
    const float* frames = (const float*)d_in[0];
    const float* text   = (const float*)d_in[1];
    const float* Wa     = (const float*)d_in[2];
    const float* Ua     = (const float*)d_in[3];
    const float* Va     = (const float*)d_in[4];
    const float* ba     = (const float*)d_in[5];
    float* out          = (float*)d_out;

    float *uh, *partial, *att, *wpart;
    __nv_bfloat16* WaT;
    cudaGetSymbolAddress((void**)&uh, g_uh);
    cudaGetSymbolAddress((void**)&partial, g_partial);
    cudaGetSymbolAddress((void**)&att, g_att);
    cudaGetSymbolAddress((void**)&WaT, g_WaT);
    cudaGetSymbolAddress((void**)&wpart, g_wpart);

    cudaFuncSetAttribute(score_hmma_kernel,
                         cudaFuncAttributeMaxDynamicSharedMemorySize, SM_TOTAL);

    transpose_kernel<<<dim3(Dz / 32, Hz / 32), dim3(32, 8)>>>(Wa, WaT);
    uh_kernel<<<dim3(Hz / 128, Bz / 8), 128>>>(text, Ua, ba, uh);
    score_hmma_kernel<<<dim3(BT / 128, NBLK), 256, SM_TOTAL>>>(
        frames, WaT, uh, Va, partial);
    softmax_kernel<<<Bz, Tz>>>(partial, att);
    wsum_kernel<<<dim3(2, Bz, 4), 256>>>(frames, att, wpart);
    wsum_combine<<<(Bz * Dz) / 1024, 256>>>(wpart, out);
}

// round 4
// speedup vs baseline: 3.3244x; 1.0165x over previous
#include <cuda_runtime.h>
#include <cuda_bf16.h>
#include <math.h>
#include <cstdint>

// Problem dims (fixed per reference)
#define Bz 64
#define Tz 512
#define Dz 2048
#define Hz 512
#define BT (Bz * Tz)          // 32768
#define NBLK 4                // H/128 h-blocks for partial scores

// Scratch (__device__ globals; allocation-free rule)
__device__ float g_uh[Bz * Hz];
__device__ float g_partial[NBLK * BT];
__device__ float g_att[BT];
__device__ __nv_bfloat16 g_WaT[Hz * Dz];   // Wa transposed -> [H, D] bf16
__device__ float g_wpart[4 * Bz * Dz];

// ---------------------------------------------------------------------------
// helpers
// ---------------------------------------------------------------------------
__device__ __forceinline__ uint32_t smem_u32(const void* p) {
    uint32_t a;
    asm("{ .reg .u64 t; cvta.to.shared.u64 t, %1; cvt.u32.u64 %0, t; }"
        : "=r"(a) : "l"(p));
    return a;
}

#define SWZ(o) ((o) ^ (((o) >> 3) & 0x70))

__device__ __forceinline__ void ldsm4(uint32_t* a, uint32_t addr) {
    asm volatile("ldmatrix.sync.aligned.m8n8.x4.shared.b16 {%0,%1,%2,%3}, [%4];"
                 : "=r"(a[0]), "=r"(a[1]), "=r"(a[2]), "=r"(a[3]) : "r"(addr));
}
__device__ __forceinline__ void mma16816(float* c, const uint32_t* a,
                                         const uint32_t* b) {
    asm volatile(
        "mma.sync.aligned.m16n8k16.row.col.f32.bf16.bf16.f32 "
        "{%0,%1,%2,%3}, {%4,%5,%6,%7}, {%8,%9}, {%0,%1,%2,%3};"
        : "+f"(c[0]), "+f"(c[1]), "+f"(c[2]), "+f"(c[3])
        : "r"(a[0]), "r"(a[1]), "r"(a[2]), "r"(a[3]), "r"(b[0]), "r"(b[1]));
}
__device__ __forceinline__ float tanh_fast(float x) {
    float y;
    asm("tanh.approx.f32 %0, %1;" : "=f"(y) : "f"(x));
    return y;
}

// ---------------------------------------------------------------------------
// Kernel 0: WaT[n][k] = bf16(Wa[k][n])
// ---------------------------------------------------------------------------
__global__ void transpose_kernel(const float* __restrict__ Wa,
                                 __nv_bfloat16* __restrict__ WaT) {
    __shared__ float tile[32][33];
    const int k0 = blockIdx.x * 32, n0 = blockIdx.y * 32;
    for (int i = threadIdx.y; i < 32; i += 8)
        tile[i][threadIdx.x] = Wa[(size_t)(k0 + i) * Hz + n0 + threadIdx.x];
    __syncthreads();
    for (int i = threadIdx.y; i < 32; i += 8)
        WaT[(size_t)(n0 + i) * Dz + k0 + threadIdx.x] =
            __float2bfloat16(tile[threadIdx.x][i]);
}

// ---------------------------------------------------------------------------
// Kernel 1: Uh[b,h] = sum_d text[b,d] * Ua[d,h] + ba[h]   (fp32)
// ---------------------------------------------------------------------------
__global__ void uh_kernel(const float* __restrict__ text,
                          const float* __restrict__ Ua,
                          const float* __restrict__ ba,
                          float* __restrict__ uh) {
    const int h  = blockIdx.x * 128 + threadIdx.x;
    const int b0 = blockIdx.y * 8;
    float acc[8] = {0.f, 0.f, 0.f, 0.f, 0.f, 0.f, 0.f, 0.f};
    __shared__ float ts[8][32];

    for (int d0 = 0; d0 < Dz; d0 += 32) {
        for (int v = threadIdx.x; v < 8 * 32; v += 128) {
            int i = v >> 5, k = v & 31;
            ts[i][k] = text[(b0 + i) * Dz + d0 + k];
        }
        __syncthreads();
        #pragma unroll
        for (int k = 0; k < 32; k++) {
            float u = Ua[(size_t)(d0 + k) * Hz + h];
            #pragma unroll
            for (int i = 0; i < 8; i++) acc[i] = fmaf(ts[i][k], u, acc[i]);
        }
        __syncthreads();
    }
    float bav = ba[h];
    #pragma unroll
    for (int i = 0; i < 8; i++) uh[(b0 + i) * Hz + h] = acc[i] + bav;
}

// ---------------------------------------------------------------------------
// Kernel 2: bf16 HMMA score GEMM + fused tanh·Va epilogue.
// CTA: M=128 rows (one b), N=128 h. K=2048 in 32 chunks of 64.
// TRIPLE-buffered smem, ONE __syncthreads per chunk:
//   sync; storeS(chunk i+1 -> buf (i+1)%3); loadG(chunk i+2); compute(buf i%3)
// Grid: (h-block=4, row-block=256) so the 4 CTAs sharing an A tile are
// wave-adjacent -> A served from L2 (frames DRAM traffic 1GB -> 256MB).
// 8 warps as 2(M) x 4(N); warp tile 64x32; frags 4x4 m16n8.
// ---------------------------------------------------------------------------
#define ABUF(s) ((uint32_t)(s) * 16384u)            // 3 x 16KB
#define BBUF(s) (49152u + (uint32_t)(s) * 16384u)   // 3 x 16KB
#define SM_TOTAL 98304
#define NCHUNK 32

__global__ __launch_bounds__(256, 1)
void score_hmma_kernel(const float* __restrict__ frames,
                       const __nv_bfloat16* __restrict__ WaT,
                       const float* __restrict__ uh,
                       const float* __restrict__ Va,
                       float* __restrict__ partial) {
    extern __shared__ char smem[];
    const uint32_t sbase = smem_u32(smem);
    const int tid = threadIdx.x;
    const int wid = tid >> 5, lane = tid & 31;
    const int warp_m = wid & 1, warp_n = wid >> 1;    // 2 x 4
    const int wm = warp_m * 64, wn = warp_n * 32;
    const int h0   = blockIdx.x * 128;
    const int row0 = blockIdx.y * 128;

    float acc[4][4][4];
    #pragma unroll
    for (int i = 0; i < 4; i++)
        #pragma unroll
        for (int j = 0; j < 4; j++)
            #pragma unroll
            for (int e = 0; e < 4; e++) acc[i][j][e] = 0.f;

    float4 pa[8], pb[4];

    // global -> regs for chunk c
    auto loadG = [&](int c) {
        const float* fA = frames + (size_t)row0 * Dz + c * 64;
        #pragma unroll
        for (int v = 0; v < 8; v++) {
            int idx = tid + v * 256;          // 128 rows x 16 float4
            int r = idx >> 4, c4 = (idx & 15) << 2;
            pa[v] = *(const float4*)(fA + (size_t)r * Dz + c4);
        }
        const __nv_bfloat16* fB = WaT + (size_t)h0 * Dz + c * 64;
        #pragma unroll
        for (int v = 0; v < 4; v++) {
            int idx = tid + v * 256;          // 128 rows x 8 x16B
            int n = idx >> 3, k8 = (idx & 7) << 3;
            pb[v] = *(const float4*)(fB + (size_t)n * Dz + k8);
        }
    };
    // regs -> smem buffer
    auto storeS = [&](uint32_t aoff, uint32_t boff) {
        #pragma unroll
        for (int v = 0; v < 8; v++) {
            int idx = tid + v * 256;
            int r = idx >> 4, c4 = (idx & 15) << 2;
            __nv_bfloat162 p0 = __floats2bfloat162_rn(pa[v].x, pa[v].y);
            __nv_bfloat162 p1 = __floats2bfloat162_rn(pa[v].z, pa[v].w);
            uint2 pk;
            pk.x = *(uint32_t*)&p0;
            pk.y = *(uint32_t*)&p1;
            *(uint2*)(smem + aoff + SWZ((uint32_t)(r * 128 + c4 * 2))) = pk;
        }
        #pragma unroll
        for (int v = 0; v < 4; v++) {
            int idx = tid + v * 256;
            int n = idx >> 3, k8 = (idx & 7) << 3;
            *(float4*)(smem + boff + SWZ((uint32_t)(n * 128 + k8 * 2))) = pb[v];
        }
    };
    // compute on buffer (aoff, boff): 4 k16-steps
    auto compute = [&](uint32_t aoff, uint32_t boff) {
        #pragma unroll
        for (int ks = 0; ks < 4; ks++) {
            const int k16 = ks * 16;
            uint32_t bfr[4][2];
            #pragma unroll
            for (int jj = 0; jj < 2; jj++) {
                // ldsm4 covers 2 n8 blocks x 2 k-halves
                uint32_t r4[4];
                int g = lane >> 3;
                uint32_t off = (uint32_t)((wn + jj * 16 + (g >> 1) * 8 + (lane & 7)) * 128 +
                                          (k16 + (g & 1) * 8) * 2);
                ldsm4(r4, sbase + boff + SWZ(off));
                bfr[jj * 2 + 0][0] = r4[0]; bfr[jj * 2 + 0][1] = r4[1];
                bfr[jj * 2 + 1][0] = r4[2]; bfr[jj * 2 + 1][1] = r4[3];
            }
            #pragma unroll
            for (int i = 0; i < 4; i++) {
                uint32_t afr[4];
                uint32_t off = (uint32_t)((wm + i * 16 + (lane & 15)) * 128 +
                                          (k16 + (lane >> 4) * 8) * 2);
                ldsm4(afr, sbase + aoff + SWZ(off));
                #pragma unroll
                for (int j = 0; j < 4; j++)
                    mma16816(acc[i][j], afr, bfr[j]);
            }
        }
    };

    // Prologue: chunk0 -> buf0; chunk1 staged in regs
    loadG(0);
    storeS(ABUF(0), BBUF(0));
    loadG(1);

    for (int i = 0; i < NCHUNK; i++) {
        __syncthreads();   // all warps done computing chunk i-1; STS of chunk i visible
        if (i + 1 < NCHUNK) {
            const int s = (i + 1) % 3;
            storeS(ABUF(s), BBUF(s));          // regs hold chunk i+1
        }
        if (i + 2 < NCHUNK) loadG(i + 2);       // issue LDGs; land during compute
        const int s = i % 3;
        compute(ABUF(s), BBUF(s));
    }

    // ---- epilogue: tanh + Va-weighted sum over this CTA's 128 h-cols ----
    const int b = row0 >> 9;
    float va_r[8], uh_r[8];
    #pragma unroll
    for (int j = 0; j < 4; j++) {
        int col = h0 + wn + j * 8 + (lane & 3) * 2;
        va_r[j * 2 + 0] = __ldg(Va + col);
        va_r[j * 2 + 1] = __ldg(Va + col + 1);
        uh_r[j * 2 + 0] = __ldg(uh + b * Hz + col);
        uh_r[j * 2 + 1] = __ldg(uh + b * Hz + col + 1);
    }
    __syncthreads();
    float* red = (float*)smem;    // [128][4] overlay

    #pragma unroll
    for (int i = 0; i < 4; i++) {
        float s0 = 0.f, s1 = 0.f;
        #pragma unroll
        for (int j = 0; j < 4; j++) {
            s0 = fmaf(va_r[j*2+0], tanh_fast(acc[i][j][0] + uh_r[j*2+0]), s0);
            s0 = fmaf(va_r[j*2+1], tanh_fast(acc[i][j][1] + uh_r[j*2+1]), s0);
            s1 = fmaf(va_r[j*2+0], tanh_fast(acc[i][j][2] + uh_r[j*2+0]), s1);
            s1 = fmaf(va_r[j*2+1], tanh_fast(acc[i][j][3] + uh_r[j*2+1]), s1);
        }
        s0 += __shfl_xor_sync(0xffffffffu, s0, 1);
        s0 += __shfl_xor_sync(0xffffffffu, s0, 2);
        s1 += __shfl_xor_sync(0xffffffffu, s1, 1);
        s1 += __shfl_xor_sync(0xffffffffu, s1, 2);
        if ((lane & 3) == 0) {
            int r = wm + i * 16 + (lane >> 2);
            red[r * 4 + warp_n] = s0;
            red[(r + 8) * 4 + warp_n] = s1;
        }
    }
    __syncthreads();
    if (tid < 128) {
        float s = red[tid * 4] + red[tid * 4 + 1] +
                  red[tid * 4 + 2] + red[tid * 4 + 3];
        partial[(size_t)blockIdx.x * BT + row0 + tid] = s;
    }
}

// ---------------------------------------------------------------------------
// Kernel 3: sum partials + softmax over T. One block per b, 512 threads.
// ---------------------------------------------------------------------------
__global__ __launch_bounds__(512)
void softmax_kernel(const float* __restrict__ partial,
                    float* __restrict__ att) {
    const int b = blockIdx.x;
    const int t = threadIdx.x;
    float s = 0.f;
    #pragma unroll
    for (int p = 0; p < NBLK; p++)
        s += partial[(size_t)p * BT + b * Tz + t];

    __shared__ float red[Tz];
    red[t] = s;
    __syncthreads();
    for (int off = 256; off; off >>= 1) {
        if (t < off) red[t] = fmaxf(red[t], red[t + off]);
        __syncthreads();
    }
    float m = red[0];
    __syncthreads();
    float e = expf(s - m);
    red[t] = e;
    __syncthreads();
    for (int off = 256; off; off >>= 1) {
        if (t < off) red[t] += red[t + off];
        __syncthreads();
    }
    att[b * Tz + t] = e * (1.0f / red[0]);
}

// ---------------------------------------------------------------------------
// Kernel 4: wsum (4-way T split) + combine
// ---------------------------------------------------------------------------
__global__ __launch_bounds__(256)
void wsum_kernel(const float* __restrict__ frames,
                 const float* __restrict__ att,
                 float* __restrict__ wpart) {
    const int b = blockIdx.y, sp = blockIdx.z;
    const int d = (blockIdx.x * 256 + threadIdx.x) * 4;
    const int t0 = sp * 128;

    __shared__ float as[128];
    if (threadIdx.x < 128) as[threadIdx.x] = att[b * Tz + t0 + threadIdx.x];
    __syncthreads();

    const float* fb = frames + ((size_t)b * Tz + t0) * Dz + d;
    float4 a0 = {0,0,0,0}, a1 = {0,0,0,0}, a2 = {0,0,0,0}, a3 = {0,0,0,0};
    #pragma unroll 2
    for (int t = 0; t < 128; t += 4) {
        float4 f0 = *(const float4*)(fb + (size_t)(t + 0) * Dz);
        float4 f1 = *(const float4*)(fb + (size_t)(t + 1) * Dz);
        float4 f2 = *(const float4*)(fb + (size_t)(t + 2) * Dz);
        float4 f3 = *(const float4*)(fb + (size_t)(t + 3) * Dz);
        float w0 = as[t], w1 = as[t + 1], w2 = as[t + 2], w3 = as[t + 3];
        a0.x = fmaf(w0, f0.x, a0.x); a0.y = fmaf(w0, f0.y, a0.y);
        a0.z = fmaf(w0, f0.z, a0.z); a0.w = fmaf(w0, f0.w, a0.w);
        a1.x = fmaf(w1, f1.x, a1.x); a1.y = fmaf(w1, f1.y, a1.y);
        a1.z = fmaf(w1, f1.z, a1.z); a1.w = fmaf(w1, f1.w, a1.w);
        a2.x = fmaf(w2, f2.x, a2.x); a2.y = fmaf(w2, f2.y, a2.y);
        a2.z = fmaf(w2, f2.z, a2.z); a2.w = fmaf(w2, f2.w, a2.w);
        a3.x = fmaf(w3, f3.x, a3.x); a3.y = fmaf(w3, f3.y, a3.y);
        a3.z = fmaf(w3, f3.z, a3.z); a3.w = fmaf(w3, f3.w, a3.w);
    }
    float4 r;
    r.x = (a0.x + a1.x) + (a2.x + a3.x);
    r.y = (a0.y + a1.y) + (a2.y + a3.y);
    r.z = (a0.z + a1.z) + (a2.z + a3.z);
    r.w = (a0.w + a1.w) + (a2.w + a3.w);
    *(float4*)(wpart + (size_t)sp * (Bz * Dz) + b * Dz + d) = r;
}

__global__ __launch_bounds__(256)
void wsum_combine(const float* __restrict__ wpart, float* __restrict__ out) {
    const int i = (blockIdx.x * 256 + threadIdx.x) * 4;
    float4 a = *(const float4*)(wpart + i);
    float4 b4 = *(const float4*)(wpart + 1 * (Bz * Dz) + i);
    float4 c = *(const float4*)(wpart + 2 * (Bz * Dz) + i);
    float4 d4 = *(const float4*)(wpart + 3 * (Bz * Dz) + i);
    float4 r;
    r.x = (a.x + b4.x) + (c.x + d4.x);
    r.y = (a.y + b4.y) + (c.y + d4.y);
    r.z = (a.z + b4.z) + (c.z + d4.z);
    r.w = (a.w + b4.w) + (c.w + d4.w);
    *(float4*)(out + i) = r;
}

// ---------------------------------------------------------------------------
extern "C" void kernel_launch(void* const* d_in, const int* in_sizes, int n_in,
                              void* d_out, int out_size) {
    const float* frames = (const float*)d_in[0];
    const float* text   = (const float*)d_in[1];
    const float* Wa     = (const float*)d_in[2];
    const float* Ua     = (const float*)d_in[3];
    const float* Va     = (const float*)d_in[4];
    const float* ba     = (const float*)d_in[5];
    float* out          = (float*)d_out;

    float *uh, *partial, *att, *wpart;
    __nv_bfloat16* WaT;
    cudaGetSymbolAddress((void**)&uh, g_uh);
    cudaGetSymbolAddress((void**)&partial, g_partial);
    cudaGetSymbolAddress((void**)&att, g_att);
    cudaGetSymbolAddress((void**)&WaT, g_WaT);
    cudaGetSymbolAddress((void**)&wpart, g_wpart);

    cudaFuncSetAttribute(score_hmma_kernel,
                         cudaFuncAttributeMaxDynamicSharedMemorySize, SM_TOTAL);

    transpose_kernel<<<dim3(Dz / 32, Hz / 32), dim3(32, 8)>>>(Wa, WaT);
    uh_kernel<<<dim3(Hz / 128, Bz / 8), 128>>>(text, Ua, ba, uh);
    // grid: x = h-block (4), y = row-block (256) -> A-tile L2 reuse
    score_hmma_kernel<<<dim3(NBLK, BT / 128), 256, SM_TOTAL>>>(
        frames, WaT, uh, Va, partial);
    softmax_kernel<<<Bz, Tz>>>(partial, att);
    wsum_kernel<<<dim3(2, Bz, 4), 256>>>(frames, att, wpart);
    wsum_combine<<<(Bz * Dz) / 1024, 256>>>(wpart, out);
}